// round 13
// baseline (speedup 1.0000x reference)
#include <cuda_runtime.h>

// VectorNet fused, round 11: R9 structure + packed fp32 GEMM (fma.rn.f32x2 /
// SASS FFMA2, 2 fp32 FMAs per issue slot). Bit-exact vs scalar fp32.
// Persistent blocks, 512 thr = two 256-thr halves, 2 polys/half/tile.
// B=32, NPOLY=256, VPP=64, L=32, PLEN=256

#define NB 32
#define NPOLY_ 256
#define NQUADS 2048   // 32 batches * 64 quads (4 polys per block-tile)
#define MAIN_GRID 148

typedef unsigned long long u64;

__device__ float g_agg[NB * NPOLY_ * 128];  // 4 MB scratch

// packed helpers
#define FMA2(d, x, w) \
    asm("fma.rn.f32x2 %0, %1, %2, %0;" : "+l"(d) : "l"(x), "l"(w))
#define PACK2(dst, f) \
    asm("mov.b64 %0, {%1, %1};" : "=l"(dst) : "f"(f))
#define UNPACK2(lo, hi, v) \
    asm("mov.b64 {%0, %1}, %2;" : "=f"(lo), "=f"(hi) : "l"(v))

// half-local barrier: 256 threads, barrier id 1 or 2
__device__ __forceinline__ void hbar(int hp) {
    asm volatile("bar.sync %0, 256;" :: "r"(hp + 1) : "memory");
}

// ---------------------------------------------------------------------------
// Stacked GEMM: (128 x OUT_C) = x(128 x K) @ W(K x OUT_C) + sterm(poly),
// then LayerNorm+ReLU. 256 threads. Thread tile R rows x 8 cols (4 col-pairs,
// packed f32x2). Rows of one thread lie in a single poly.
// STORE=true : write h to hs (row stride HLD).
// STORE=false: per-thread row-max only -> hs[rg*HLD + c0..] (partials).
// st: sterm base; per-poly stride ST_STRIDE (0 => shared bias).
// ---------------------------------------------------------------------------
template <int K, int OUT_C, int R, int XLD, int HLD, bool STORE, int ST_STRIDE>
__device__ __forceinline__ void gemm_ln_relu(
    const float* __restrict__ xs, float* __restrict__ hs,
    const float* __restrict__ Ws, const float* __restrict__ gs,
    const float* __restrict__ bes, const float* __restrict__ st, int ltid)
{
    constexpr int NCG = OUT_C / 8;       // col groups
    constexpr int RG  = (R > 4) ? 4 : R; // rows per x-load group (reg cap)
    constexpr int NG  = R / RG;
    const int rg = ltid / NCG, cg = ltid % NCG;
    const int r0 = rg * R, c0 = cg * 8;
    const int poly = r0 >> 6;
    const float* sb = st + poly * ST_STRIDE;

    u64 acc[R][4];                        // 4 packed col-pairs per row
    {
        ulonglong2 s01 = *reinterpret_cast<const ulonglong2*>(sb + c0);
        ulonglong2 s23 = *reinterpret_cast<const ulonglong2*>(sb + c0 + 4);
#pragma unroll
        for (int i = 0; i < R; i++) {
            acc[i][0] = s01.x; acc[i][1] = s01.y;
            acc[i][2] = s23.x; acc[i][3] = s23.y;
        }
    }

#pragma unroll 2
    for (int k0 = 0; k0 < K; k0 += 4) {
#pragma unroll
        for (int g = 0; g < NG; g++) {
            float xv[RG][4];
#pragma unroll
            for (int i = 0; i < RG; i++) {
                float4 t = *reinterpret_cast<const float4*>(
                    xs + (r0 + g * RG + i) * XLD + k0);
                xv[i][0] = t.x; xv[i][1] = t.y; xv[i][2] = t.z; xv[i][3] = t.w;
            }
#pragma unroll
            for (int kk = 0; kk < 4; kk++) {
                ulonglong2 wA = *reinterpret_cast<const ulonglong2*>(
                    Ws + (k0 + kk) * OUT_C + c0);
                ulonglong2 wB = *reinterpret_cast<const ulonglong2*>(
                    Ws + (k0 + kk) * OUT_C + c0 + 4);
#pragma unroll
                for (int i = 0; i < RG; i++) {
                    u64 xx;
                    PACK2(xx, xv[i][kk]);
                    u64* a = acc[g * RG + i];
                    FMA2(a[0], xx, wA.x);
                    FMA2(a[1], xx, wA.y);
                    FMA2(a[2], xx, wB.x);
                    FMA2(a[3], xx, wB.y);
                }
            }
        }
    }

    const float invC = 1.0f / (float)OUT_C;
    float mx[8];
    if (!STORE) {
#pragma unroll
        for (int j = 0; j < 8; j++) mx[j] = 0.f;
    }

#pragma unroll
    for (int i = 0; i < R; i++) {
        float a[8];
#pragma unroll
        for (int j = 0; j < 4; j++) UNPACK2(a[2 * j], a[2 * j + 1], acc[i][j]);

        float s = 0.f, s2 = 0.f;
#pragma unroll
        for (int j = 0; j < 8; j++) {
            s += a[j];
            s2 = fmaf(a[j], a[j], s2);
        }
#pragma unroll
        for (int o = NCG / 2; o > 0; o >>= 1) {
            s  += __shfl_xor_sync(0xffffffffu, s, o);
            s2 += __shfl_xor_sync(0xffffffffu, s2, o);
        }
        float mu   = s * invC;
        float var  = fmaf(-mu, mu, s2 * invC);
        float rstd = rsqrtf(var + 1e-5f);
        float v[8];
#pragma unroll
        for (int j = 0; j < 8; j++)
            v[j] = fmaxf(fmaf((a[j] - mu) * rstd, gs[c0 + j], bes[c0 + j]), 0.f);

        if (STORE) {
            float4 o1 = {v[0], v[1], v[2], v[3]};
            float4 o2 = {v[4], v[5], v[6], v[7]};
            *reinterpret_cast<float4*>(hs + (r0 + i) * HLD + c0)     = o1;
            *reinterpret_cast<float4*>(hs + (r0 + i) * HLD + c0 + 4) = o2;
        } else {
#pragma unroll
            for (int j = 0; j < 8; j++) mx[j] = fmaxf(mx[j], v[j]);
        }
    }

    if (!STORE) {
        float4 m1 = {mx[0], mx[1], mx[2], mx[3]};
        float4 m2 = {mx[4], mx[5], mx[6], mx[7]};
        *reinterpret_cast<float4*>(hs + rg * HLD + c0)     = m1;
        *reinterpret_cast<float4*>(hs + rg * HLD + c0 + 4) = m2;
    }
}

// colmax partial pass over 128 stacked rows (post-ReLU, >= 0)
template <int NC, int LD>
__device__ __forceinline__ void colmax_part(const float* __restrict__ hs,
                                            float* __restrict__ part, int ltid)
{
    constexpr int NCH = 256 / NC;     // chunks (first half poly0, second poly1)
    constexpr int RP  = 128 / NCH;    // rows per chunk
    const int col = ltid % NC, ch = ltid / NC;
    float m = 0.f;
#pragma unroll
    for (int r = 0; r < RP; r++) m = fmaxf(m, hs[(ch * RP + r) * LD + col]);
    part[ch * NC + col] = m;
}

// ---------------------------------------------------------------------------
// Persistent main kernel: grid=148, 512 threads = two decoupled 256-thr
// halves; each half runs 2 polys per tile (stacked 128-row GEMMs).
// Per-half smem floats: bufA 8704 (x0 LD36 / h1 LD68), bufB 4608 (h0 LD36 /
// L2 max partials 16x128), agg 256, sterm 256, part 256  -> 14080.
// ---------------------------------------------------------------------------
__global__ void __launch_bounds__(512, 1)
vn_main_kernel(const float* __restrict__ data,
               const float* __restrict__ W0g, const float* __restrict__ b0g,
               const float* __restrict__ g0g, const float* __restrict__ be0g,
               const float* __restrict__ W1g, const float* __restrict__ b1g,
               const float* __restrict__ g1g, const float* __restrict__ be1g,
               const float* __restrict__ W2g, const float* __restrict__ b2g,
               const float* __restrict__ g2g, const float* __restrict__ be2g)
{
    extern __shared__ float sm[];
    float* W0s  = sm;            // 1024
    float* W1s  = sm + 1024;     // 4096
    float* W2s  = sm + 5120;     // 16384
    float* g0s  = sm + 21504;  float* be0s = sm + 21536;
    float* g1s  = sm + 21568;  float* be1s = sm + 21632;
    float* g2s  = sm + 21696;  float* be2s = sm + 21824;
    float* b0s  = sm + 21952;  float* b1s  = sm + 21984;
    float* b2s  = sm + 22048;  // weights end at 22176

    const int tid  = threadIdx.x;
    const int hp   = tid >> 8;        // which half
    const int ltid = tid & 255;

    float* pb    = sm + 22176 + hp * 14080;
    float* bufA  = pb;           // 8704: x0 @LD36 then h1 @LD68 (128 rows)
    float* bufB  = pb + 8704;    // 4608: h0 @LD36; reused as L2 partials 16x128
    float* agg   = pb + 13312;   // 256 (2 polys)
    float* sterm = pb + 13568;   // 256 (2 polys)
    float* part  = pb + 13824;   // 256

    // stage weights once per block (block-wide)
    for (int i = tid; i < 256;  i += 512) ((float4*)W0s)[i] = ((const float4*)W0g)[i];
    for (int i = tid; i < 1024; i += 512) ((float4*)W1s)[i] = ((const float4*)W1g)[i];
    for (int i = tid; i < 4096; i += 512) ((float4*)W2s)[i] = ((const float4*)W2g)[i];
    if (tid < 32)  { g0s[tid] = g0g[tid]; be0s[tid] = be0g[tid]; b0s[tid] = b0g[tid]; }
    else if (tid < 96)  { g1s[tid-32] = g1g[tid-32]; be1s[tid-32] = be1g[tid-32]; b1s[tid-32] = b1g[tid-32]; }
    else if (tid < 224) { g2s[tid-96] = g2g[tid-96]; be2s[tid-96] = be2g[tid-96]; b2s[tid-96] = b2g[tid-96]; }
    __syncthreads();   // only block-wide sync; halves free-run after this

    // ---- initial x0 load: 2 polys = 128 rows x 32 ch, channel 31 zeroed ----
    {
        const int quad = blockIdx.x;
        const int b = quad >> 6, qi = quad & 63;
        const int poly0 = qi * 4 + hp * 2;
        const float* base = data + ((size_t)b * 16385 + 1 + (size_t)poly0 * 64) * 32;
#pragma unroll
        for (int t = 0; t < 4; t++) {
            int e4 = ltid + t * 256;
            float4 v = ((const float4*)base)[e4];
            int r = e4 >> 3, kq = e4 & 7;
            if (kq == 7) v.w = 0.f;
            *reinterpret_cast<float4*>(bufA + r * 36 + kq * 4) = v;
        }
    }
    hbar(hp);

    for (int quad = blockIdx.x; quad < NQUADS; quad += MAIN_GRID) {
        const int b = quad >> 6, qi = quad & 63;
        const int poly0 = qi * 4 + hp * 2;

        // ---- layer 0 ----  (bufA x0 LD36 -> bufB h0 LD36), sterm = b0 shared
        gemm_ln_relu<32, 32, 2, 36, 36, true, 0>(bufA, bufB, W0s, g0s, be0s, b0s, ltid);
        hbar(hp);
        colmax_part<32, 36>(bufB, part, ltid);          // 8 chunks x 32
        hbar(hp);
        if (ltid < 64) {                                 // agg0[poly*32+col]
            int poly = ltid >> 5, col = ltid & 31;
            float m = part[(poly * 4) * 32 + col];
#pragma unroll
            for (int c = 1; c < 4; c++) m = fmaxf(m, part[(poly * 4 + c) * 32 + col]);
            agg[poly * 32 + col] = m;
        }
        hbar(hp);
        if (ltid < 128) {                                // sterm1 = b1 + agg0 @ W1low
            int poly = ltid >> 6, col = ltid & 63;
            float v = b1s[col];
#pragma unroll
            for (int k = 0; k < 32; k++)
                v = fmaf(agg[poly * 32 + k], W1s[(32 + k) * 64 + col], v);
            sterm[poly * 64 + col] = v;
        }
        hbar(hp);

        // ---- layer 1 ----  (bufB h0 LD36 -> bufA h1 LD68)
        gemm_ln_relu<32, 64, 4, 36, 68, true, 64>(bufB, bufA, W1s, g1s, be1s, sterm, ltid);
        hbar(hp);
        colmax_part<64, 68>(bufA, part, ltid);          // 4 chunks x 64
        hbar(hp);
        if (ltid < 128) {                                // agg1[poly*64+col]
            int poly = ltid >> 6, col = ltid & 63;
            agg[poly * 64 + col] =
                fmaxf(part[(poly * 2) * 64 + col], part[(poly * 2 + 1) * 64 + col]);
        }
        hbar(hp);
        {                                                // sterm2 = b2 + agg1 @ W2low
            int poly = ltid >> 7, col = ltid & 127;
            float v = b2s[col];
#pragma unroll
            for (int k = 0; k < 64; k++)
                v = fmaf(agg[poly * 64 + k], W2s[(64 + k) * 128 + col], v);
            sterm[ltid] = v;
        }
        hbar(hp);

        // ---- layer 2 ----  (bufA h1 LD68 -> bufB rowgroup max partials 16x128)
        gemm_ln_relu<64, 128, 8, 68, 128, false, 128>(bufA, bufB, W2s, g2s, be2s, sterm, ltid);
        hbar(hp);

        // ---- final phase: next x0 LDG issue, agg2 reduce+store, x0 STS ----
        int nq = quad + MAIN_GRID;
        if (nq >= NQUADS) nq = quad;                    // harmless reload on last
        const int nb = nq >> 6, nqi = nq & 63;
        const int npoly0 = nqi * 4 + hp * 2;
        const float* nbase = data + ((size_t)nb * 16385 + 1 + (size_t)npoly0 * 64) * 32;
        float4 xp[4];
#pragma unroll
        for (int t = 0; t < 4; t++) xp[t] = ((const float4*)nbase)[ltid + t * 256];

        {   // agg2 over 8 rowgroups per poly -> g_agg
            int poly = ltid >> 7, col = ltid & 127;
            float m = bufB[(poly * 8) * 128 + col];
#pragma unroll
            for (int r = 1; r < 8; r++) m = fmaxf(m, bufB[(poly * 8 + r) * 128 + col]);
            g_agg[((size_t)(b * 256 + poly0 + poly)) * 128 + col] = m;
        }

#pragma unroll
        for (int t = 0; t < 4; t++) {
            int e4 = ltid + t * 256;
            int r = e4 >> 3, kq = e4 & 7;
            if (kq == 7) xp[t].w = 0.f;
            *reinterpret_cast<float4*>(bufA + r * 36 + kq * 4) = xp[t];
        }
        hbar(hp);
    }
}

// ---------------------------------------------------------------------------
// Attention kernel: one block per batch, 512 threads, split partials.
// q = P[agent]@Wq'+bq; t = Wk'q; scores = P@t/16; softmax; out = (att@P)@Wv'+bv
// (Wx' = Wx[:128]+Wx[128:] since P halves are identical; bk drops in softmax)
// ---------------------------------------------------------------------------
__global__ void __launch_bounds__(512, 1)
vn_attn_kernel(const float* __restrict__ data,
               const float* __restrict__ Wq, const float* __restrict__ bq,
               const float* __restrict__ Wk,
               const float* __restrict__ Wv, const float* __restrict__ bv,
               float* __restrict__ out)
{
    extern __shared__ float sm[];
    float* Pb   = sm;            // 256*132 = 33792
    float* q    = Pb + 33792;    // 256
    float* t    = q + 256;       // 128
    float* sc   = t + 128;       // 256
    float* w128 = sc + 256;      // 128
    float* red  = w128 + 128;    // 32
    float* part = red + 32;      // 512

    const int tid = threadIdx.x, lane = tid & 31, w = tid >> 5;
    const int b = blockIdx.x;

    const float* P = g_agg + (size_t)b * 256 * 128;
    for (int e4 = tid; e4 < 8192; e4 += 512) {
        int p = e4 >> 5, j4 = e4 & 31;
        *reinterpret_cast<float4*>(Pb + p * 132 + j4 * 4) = ((const float4*)P)[e4];
    }
    if (tid == 0) red[0] = data[(size_t)b * 16385 * 32];  // agent id
    __syncthreads();
    const int aid = (int)red[0];

    // q = P[agent] @ Wq' + bq  (k-split 2-way)
    {
        const int col = tid & 255, half = tid >> 8;
        const float* pr = Pb + aid * 132;
        float s = 0.f;
        for (int j = half * 64; j < half * 64 + 64; j++)
            s = fmaf(pr[j], Wq[j * 256 + col] + Wq[(j + 128) * 256 + col], s);
        part[half * 256 + col] = s;
    }
    __syncthreads();
    if (tid < 256) q[tid] = bq[tid] + part[tid] + part[256 + tid];
    __syncthreads();

    // t = Wk' @ q  (16 warps x 8 rows)
    for (int jj = 0; jj < 8; jj++) {
        int j = w * 8 + jj;
        float a = 0.f;
#pragma unroll
        for (int m = 0; m < 8; m++) {
            int c = lane + m * 32;
            a = fmaf(Wk[j * 256 + c] + Wk[(j + 128) * 256 + c], q[c], a);
        }
#pragma unroll
        for (int o = 16; o > 0; o >>= 1) a += __shfl_xor_sync(0xffffffffu, a, o);
        if (lane == 0) t[j] = a;
    }
    __syncthreads();

    // scores[p] = (P[p].t)/16  (16 warps x 16 rows)
    for (int pp = 0; pp < 16; pp++) {
        int p = w * 16 + pp;
        float a = 0.f;
#pragma unroll
        for (int m = 0; m < 4; m++) {
            int j = lane + m * 32;
            a = fmaf(Pb[p * 132 + j], t[j], a);
        }
#pragma unroll
        for (int o = 16; o > 0; o >>= 1) a += __shfl_xor_sync(0xffffffffu, a, o);
        if (lane == 0) sc[p] = a * 0.0625f;
    }
    __syncthreads();

    // softmax over 256 (threads 0..255)
    float v = 0.f, e = 0.f;
    if (tid < 256) {
        v = sc[tid];
        float mx = v;
#pragma unroll
        for (int o = 16; o > 0; o >>= 1) mx = fmaxf(mx, __shfl_xor_sync(0xffffffffu, mx, o));
        if (lane == 0) red[w] = mx;
    }
    __syncthreads();
    if (tid == 0) {
        float M = red[0];
        for (int i = 1; i < 8; i++) M = fmaxf(M, red[i]);
        red[8] = M;
    }
    __syncthreads();
    if (tid < 256) {
        e = __expf(v - red[8]);
        float se = e;
#pragma unroll
        for (int o = 16; o > 0; o >>= 1) se += __shfl_xor_sync(0xffffffffu, se, o);
        if (lane == 0) red[16 + w] = se;
    }
    __syncthreads();
    if (tid == 0) {
        float S = 0.f;
        for (int i = 0; i < 8; i++) S += red[16 + i];
        red[24] = 1.f / S;
    }
    __syncthreads();
    if (tid < 256) sc[tid] = e * red[24];
    __syncthreads();

    // w128 = att @ P  (4-way row split)
    {
        const int col = tid & 127, seg = tid >> 7;
        float a = 0.f;
        for (int p = seg * 64; p < seg * 64 + 64; p++)
            a = fmaf(sc[p], Pb[p * 132 + col], a);
        part[seg * 128 + col] = a;
    }
    __syncthreads();
    if (tid < 128)
        w128[tid] = part[tid] + part[128 + tid] + part[256 + tid] + part[384 + tid];
    __syncthreads();

    // out = w128 @ Wv' + bv  (k-split 2-way)
    {
        const int col = tid & 255, half = tid >> 8;
        float o = 0.f;
        for (int j = half * 64; j < half * 64 + 64; j++)
            o = fmaf(w128[j], Wv[j * 256 + col] + Wv[(j + 128) * 256 + col], o);
        part[half * 256 + col] = o;
    }
    __syncthreads();
    if (tid < 256) out[b * 256 + tid] = bv[tid] + part[tid] + part[256 + tid];
}

// ---------------------------------------------------------------------------
extern "C" void kernel_launch(void* const* d_in, const int* in_sizes, int n_in,
                              void* d_out, int out_size)
{
    const float* data = (const float*)d_in[0];
    const float* W0  = (const float*)d_in[1];
    const float* b0  = (const float*)d_in[2];
    const float* g0  = (const float*)d_in[3];
    const float* be0 = (const float*)d_in[4];
    const float* W1  = (const float*)d_in[5];
    const float* b1  = (const float*)d_in[6];
    const float* g1  = (const float*)d_in[7];
    const float* be1 = (const float*)d_in[8];
    const float* W2  = (const float*)d_in[9];
    const float* b2  = (const float*)d_in[10];
    const float* g2  = (const float*)d_in[11];
    const float* be2 = (const float*)d_in[12];
    const float* Wq  = (const float*)d_in[13];
    const float* bq  = (const float*)d_in[14];
    const float* Wk  = (const float*)d_in[15];
    // d_in[16] = bk: softmax-invariant, unused
    const float* Wv  = (const float*)d_in[17];
    const float* bv  = (const float*)d_in[18];
    float* out = (float*)d_out;

    const size_t smA = (size_t)(22176 + 2 * 14080) * sizeof(float);  // ~196.6 KB
    const size_t smB = (size_t)(33792 + 256 + 128 + 256 + 128 + 32 + 512) * sizeof(float);
    cudaFuncSetAttribute(vn_main_kernel, cudaFuncAttributeMaxDynamicSharedMemorySize, (int)smA);
    cudaFuncSetAttribute(vn_attn_kernel, cudaFuncAttributeMaxDynamicSharedMemorySize, (int)smB);

    vn_main_kernel<<<MAIN_GRID, 512, smA>>>(data, W0, b0, g0, be0,
                                            W1, b1, g1, be1, W2, b2, g2, be2);
    vn_attn_kernel<<<NB, 512, smB>>>(data, Wq, bq, Wk, Wv, bv, out);
}